// round 4
// baseline (speedup 1.0000x reference)
#include <cuda_runtime.h>
#include <math.h>

// MultiLayerElmanRNN: persistent wavefront kernel.
// Grid = 4 layers x 32 slices = 128 CTAs (all resident on 148 SMs).
// Each CTA owns 16 hidden rows of one layer; weights live in SMEM for the
// whole kernel. Cells synchronize through global arrival counters.
// d_out (seq, L, B, H) itself is the activation storage between cells.

#define SEQ       512
#define BATCH     64
#define HID       512
#define NL        4
#define SLICES    32          // CTAs per layer
#define ROWS      16          // hidden rows per CTA
#define NTHREADS  128
#define WS        516         // weight row stride in floats (bank-conflict pad)
#define AS        65          // activation row stride in floats (conflict-free pad)
#define CHUNK     64          // k-chunk staged in SMEM

#define SMEM_BYTES ((2 * ROWS * WS + BATCH * AS) * 4)

__device__ int g_cnt[NL * SEQ];

__global__ void reset_kernel() {
    int i = blockIdx.x * blockDim.x + threadIdx.x;
    if (i < NL * SEQ) g_cnt[i] = 0;
}

__global__ __launch_bounds__(NTHREADS, 1)
void rnn_kernel(const float* __restrict__ x,
                const float* __restrict__ W_ih,
                const float* __restrict__ W_hh,
                const float* __restrict__ b_ih,
                const float* __restrict__ b_hh,
                float* out) {
    extern __shared__ float smem[];
    float* w_ih_s = smem;                    // [ROWS][WS]
    float* w_hh_s = smem + ROWS * WS;        // [ROWS][WS]
    float* act_s  = smem + 2 * ROWS * WS;    // [BATCH][AS]

    const int l    = blockIdx.x / SLICES;
    const int s    = blockIdx.x % SLICES;
    const int tid  = threadIdx.x;
    const int row0 = s * ROWS;

    // ---- load this CTA's weight rows into SMEM (once) ----
    {
        const float4* gih = (const float4*)(W_ih + (size_t)l * HID * HID + (size_t)row0 * HID);
        const float4* ghh = (const float4*)(W_hh + (size_t)l * HID * HID + (size_t)row0 * HID);
        for (int p = tid; p < ROWS * (HID / 4); p += NTHREADS) {
            int r = p / (HID / 4);
            int c = p % (HID / 4);
            float4 v = gih[(size_t)r * (HID / 4) + c];
            *(float4*)&w_ih_s[r * WS + c * 4] = v;
            float4 u = ghh[(size_t)r * (HID / 4) + c];
            *(float4*)&w_hh_s[r * WS + c * 4] = u;
        }
    }

    // thread tile: 2 rows (r0, r0+1) x 4 batches (q, q+16, q+32, q+48)
    const int q  = tid & 15;
    const int rg = tid >> 4;      // 0..7
    const int r0 = rg * 2;

    const float bias0 = b_ih[l * HID + row0 + r0]     + b_hh[l * HID + row0 + r0];
    const float bias1 = b_ih[l * HID + row0 + r0 + 1] + b_hh[l * HID + row0 + r0 + 1];

    __syncthreads();

    volatile int* cnt = g_cnt;

    for (int t = 0; t < SEQ; t++) {
        // ---- wait for dependencies: (t, l-1) and (t-1, l) fully published ----
        if (tid == 0) {
            if (l > 0) { while (cnt[(l - 1) * SEQ + t] < SLICES) __nanosleep(40); }
            if (t > 0) { while (cnt[l * SEQ + (t - 1)] < SLICES) __nanosleep(40); }
        }
        __syncthreads();
        __threadfence();   // acquire: order subsequent global reads after the flag

        float acc00 = bias0, acc01 = bias0, acc02 = bias0, acc03 = bias0;
        float acc10 = bias1, acc11 = bias1, acc12 = bias1, acc13 = bias1;

        const float* inp = (l == 0)
            ? (x + (size_t)t * BATCH * HID)
            : (out + ((size_t)t * NL + (l - 1)) * (BATCH * HID));

        const int nhalf = (t == 0) ? 1 : 2;   // t==0: h_prev = 0, skip recurrent GEMM
        for (int half = 0; half < nhalf; half++) {
            const float* act = (half == 0)
                ? inp
                : (out + ((size_t)(t - 1) * NL + l) * (BATCH * HID));
            const float* wsm = (half == 0) ? w_ih_s : w_hh_s;

            for (int c0 = 0; c0 < HID; c0 += CHUNK) {
                __syncthreads();
                // stage act chunk [64 b][64 k] into SMEM (coalesced gmem reads)
                #pragma unroll
                for (int rr = 0; rr < 8; rr++) {
                    int p  = tid + rr * NTHREADS;    // 0..1023
                    int b  = p >> 4;
                    int kq = (p & 15) << 2;
                    float4 v = *(const float4*)(act + (size_t)b * HID + c0 + kq);
                    float* d = &act_s[b * AS + kq];
                    d[0] = v.x; d[1] = v.y; d[2] = v.z; d[3] = v.w;
                }
                __syncthreads();

                const float* wb = wsm + r0 * WS + c0;
                const float* ab = act_s + q * AS;
                #pragma unroll 8
                for (int kk = 0; kk < CHUNK; kk++) {
                    float w0 = wb[kk];
                    float w1 = wb[WS + kk];
                    float a0 = ab[kk];
                    float a1 = ab[16 * AS + kk];
                    float a2 = ab[32 * AS + kk];
                    float a3 = ab[48 * AS + kk];
                    acc00 = fmaf(w0, a0, acc00);
                    acc01 = fmaf(w0, a1, acc01);
                    acc02 = fmaf(w0, a2, acc02);
                    acc03 = fmaf(w0, a3, acc03);
                    acc10 = fmaf(w1, a0, acc10);
                    acc11 = fmaf(w1, a1, acc11);
                    acc12 = fmaf(w1, a2, acc12);
                    acc13 = fmaf(w1, a3, acc13);
                }
            }
        }

        // ---- tanh + store (h rows r0,r0+1 are consecutive -> float2) ----
        {
            size_t obase = ((size_t)t * NL + l) * (BATCH * HID) + row0 + r0;
            *(float2*)(out + obase + (size_t)(q     ) * HID) = make_float2(tanhf(acc00), tanhf(acc10));
            *(float2*)(out + obase + (size_t)(q + 16) * HID) = make_float2(tanhf(acc01), tanhf(acc11));
            *(float2*)(out + obase + (size_t)(q + 32) * HID) = make_float2(tanhf(acc02), tanhf(acc12));
            *(float2*)(out + obase + (size_t)(q + 48) * HID) = make_float2(tanhf(acc03), tanhf(acc13));
        }

        // ---- publish: all stores visible, then arrive on counter ----
        __threadfence();
        __syncthreads();
        if (tid == 0) atomicAdd(&g_cnt[l * SEQ + t], 1);
    }
}

extern "C" void kernel_launch(void* const* d_in, const int* in_sizes, int n_in,
                              void* d_out, int out_size) {
    const float* x    = (const float*)d_in[0];
    const float* W_ih = (const float*)d_in[1];
    const float* W_hh = (const float*)d_in[2];
    const float* b_ih = (const float*)d_in[3];
    const float* b_hh = (const float*)d_in[4];
    float* out = (float*)d_out;

    cudaFuncSetAttribute(rnn_kernel, cudaFuncAttributeMaxDynamicSharedMemorySize, SMEM_BYTES);

    reset_kernel<<<2, 1024>>>();
    rnn_kernel<<<NL * SLICES, NTHREADS, SMEM_BYTES>>>(x, W_ih, W_hh, b_ih, b_hh, out);
}

// round 5
// speedup vs baseline: 1.0771x; 1.0771x over previous
#include <cuda_runtime.h>
#include <math.h>
#include <stdint.h>

// MultiLayerElmanRNN — persistent wavefront kernel, round 4.
// 128 CTAs (4 layers x 32 slices), 256 threads (2 warps/SMSP).
// Weights transposed + packed in SMEM for f32x2 FFMA2; act staged whole-half
// with conflict-free 516-float row stride. hh-half computed before ih-half.

#define SEQ       512
#define BATCH     64
#define HID       512
#define NL        4
#define SLICES    32
#define ROWS      16
#define NTHREADS  256
#define AS        516                 // act row stride (floats): 16B-aligned, conflict-free
#define WT        16                  // wT floats per k (16 rows)
#define WT_FLOATS (HID * WT)          // 8192 floats per weight matrix

#define SMEM_FLOATS (2 * WT_FLOATS + BATCH * AS)
#define SMEM_BYTES  (SMEM_FLOATS * 4)   // 197632 bytes

__device__ int g_cnt[NL * SEQ];

__global__ void reset_kernel() {
    int i = blockIdx.x * blockDim.x + threadIdx.x;
    if (i < NL * SEQ) g_cnt[i] = 0;
}

__device__ __forceinline__ unsigned long long pack_pair(float lo, float hi) {
    unsigned long long r;
    asm("mov.b64 %0, {%1, %2};" : "=l"(r) : "f"(lo), "f"(hi));
    return r;
}

__device__ __forceinline__ void unpack_pair(unsigned long long p, float& lo, float& hi) {
    asm("mov.b64 {%0, %1}, %2;" : "=f"(lo), "=f"(hi) : "l"(p));
}

// One 512-K GEMM half: acc01/acc23 are f32x2 pairs over 4 output rows.
__device__ __forceinline__ void gemm_half(uint32_t wa, uint32_t aa,
                                          unsigned long long& acc01,
                                          unsigned long long& acc23) {
    uint32_t wk = wa;
    uint32_t ak = aa;
#pragma unroll 16
    for (int k4 = 0; k4 < HID / 4; k4++) {
        float ax, ay, az, aw;
        asm("ld.shared.v4.f32 {%0,%1,%2,%3}, [%4];"
            : "=f"(ax), "=f"(ay), "=f"(az), "=f"(aw) : "r"(ak));
        unsigned long long w01, w23, a2;

        asm("ld.shared.v2.u64 {%0,%1}, [%2];" : "=l"(w01), "=l"(w23) : "r"(wk));
        asm("mov.b64 %0, {%1,%1};" : "=l"(a2) : "f"(ax));
        asm("fma.rn.f32x2 %0, %1, %2, %3;" : "=l"(acc01) : "l"(w01), "l"(a2), "l"(acc01));
        asm("fma.rn.f32x2 %0, %1, %2, %3;" : "=l"(acc23) : "l"(w23), "l"(a2), "l"(acc23));

        asm("ld.shared.v2.u64 {%0,%1}, [%2+64];" : "=l"(w01), "=l"(w23) : "r"(wk));
        asm("mov.b64 %0, {%1,%1};" : "=l"(a2) : "f"(ay));
        asm("fma.rn.f32x2 %0, %1, %2, %3;" : "=l"(acc01) : "l"(w01), "l"(a2), "l"(acc01));
        asm("fma.rn.f32x2 %0, %1, %2, %3;" : "=l"(acc23) : "l"(w23), "l"(a2), "l"(acc23));

        asm("ld.shared.v2.u64 {%0,%1}, [%2+128];" : "=l"(w01), "=l"(w23) : "r"(wk));
        asm("mov.b64 %0, {%1,%1};" : "=l"(a2) : "f"(az));
        asm("fma.rn.f32x2 %0, %1, %2, %3;" : "=l"(acc01) : "l"(w01), "l"(a2), "l"(acc01));
        asm("fma.rn.f32x2 %0, %1, %2, %3;" : "=l"(acc23) : "l"(w23), "l"(a2), "l"(acc23));

        asm("ld.shared.v2.u64 {%0,%1}, [%2+192];" : "=l"(w01), "=l"(w23) : "r"(wk));
        asm("mov.b64 %0, {%1,%1};" : "=l"(a2) : "f"(aw));
        asm("fma.rn.f32x2 %0, %1, %2, %3;" : "=l"(acc01) : "l"(w01), "l"(a2), "l"(acc01));
        asm("fma.rn.f32x2 %0, %1, %2, %3;" : "=l"(acc23) : "l"(w23), "l"(a2), "l"(acc23));

        wk += 256;   // 4 k * 16 floats * 4B
        ak += 16;    // 4 floats
    }
}

__global__ __launch_bounds__(NTHREADS, 1)
void rnn_kernel(const float* __restrict__ x,
                const float* __restrict__ W_ih,
                const float* __restrict__ W_hh,
                const float* __restrict__ b_ih,
                const float* __restrict__ b_hh,
                float* __restrict__ out) {
    extern __shared__ float smem[];
    float* act_s = smem + 2 * WT_FLOATS;

    uint32_t sbase;
    asm("{ .reg .u64 t; cvta.to.shared.u64 t, %1; cvt.u32.u64 %0, t; }"
        : "=r"(sbase) : "l"(smem));
    const uint32_t wih_base = sbase;
    const uint32_t whh_base = sbase + WT_FLOATS * 4;
    const uint32_t act_base = sbase + 2 * WT_FLOATS * 4;

    const int l    = blockIdx.x / SLICES;
    const int s    = blockIdx.x % SLICES;
    const int tid  = threadIdx.x;
    const int row0 = s * ROWS;

    // ---- load + transpose this CTA's weight rows into SMEM (once) ----
    for (int p = tid; p < ROWS * HID; p += NTHREADS) {
        int r = p >> 9;          // 0..15
        int k = p & (HID - 1);   // 0..511
        smem[k * WT + r]             = W_ih[(size_t)l * HID * HID + (size_t)(row0 + r) * HID + k];
        smem[WT_FLOATS + k * WT + r] = W_hh[(size_t)l * HID * HID + (size_t)(row0 + r) * HID + k];
    }

    // thread tile: 4 rows x 1 batch
    const int b  = tid & 63;     // batch
    const int rq = tid >> 6;     // row quad 0..3 (warp-uniform)

    float bi0 = b_ih[l * HID + row0 + rq * 4 + 0] + b_hh[l * HID + row0 + rq * 4 + 0];
    float bi1 = b_ih[l * HID + row0 + rq * 4 + 1] + b_hh[l * HID + row0 + rq * 4 + 1];
    float bi2 = b_ih[l * HID + row0 + rq * 4 + 2] + b_hh[l * HID + row0 + rq * 4 + 2];
    float bi3 = b_ih[l * HID + row0 + rq * 4 + 3] + b_hh[l * HID + row0 + rq * 4 + 3];

    const uint32_t aa = act_base + (uint32_t)b * AS * 4;    // this thread's act row
    const uint32_t wa_ih = wih_base + (uint32_t)rq * 16;    // 4 bytes * 4 rows
    const uint32_t wa_hh = whh_base + (uint32_t)rq * 16;

    __syncthreads();

    volatile int* cnt = g_cnt;

    for (int t = 0; t < SEQ; t++) {
        unsigned long long acc01 = pack_pair(bi0, bi1);
        unsigned long long acc23 = pack_pair(bi2, bi3);

        // ===== recurrent half first (dep: (t-1, l) only) =====
        if (t > 0) {
            if (tid == 0) {
                while (cnt[l * SEQ + (t - 1)] < SLICES) __nanosleep(20);
            }
            __syncthreads();
            __threadfence();
            const float* src = out + ((size_t)(t - 1) * NL + l) * (BATCH * HID);
#pragma unroll 4
            for (int i = 0; i < 32; i++) {
                int p  = tid + i * NTHREADS;    // 0..8191 float4 units
                int bb = p >> 7;
                int kq = p & 127;
                float4 v = *(const float4*)(src + (size_t)bb * HID + kq * 4);
                *(float4*)&act_s[bb * AS + kq * 4] = v;
            }
            __syncthreads();
            gemm_half(wa_hh, aa, acc01, acc23);
        }

        // ===== input half (dep: (t, l-1)) =====
        if (l > 0) {
            if (tid == 0) {
                while (cnt[(l - 1) * SEQ + t] < SLICES) __nanosleep(20);
            }
        }
        __syncthreads();      // also guards act_s reuse after hh gemm
        __threadfence();
        {
            const float* src = (l == 0)
                ? (x + (size_t)t * BATCH * HID)
                : (out + ((size_t)t * NL + (l - 1)) * (BATCH * HID));
#pragma unroll 4
            for (int i = 0; i < 32; i++) {
                int p  = tid + i * NTHREADS;
                int bb = p >> 7;
                int kq = p & 127;
                float4 v = *(const float4*)(src + (size_t)bb * HID + kq * 4);
                *(float4*)&act_s[bb * AS + kq * 4] = v;
            }
            __syncthreads();
            gemm_half(wa_ih, aa, acc01, acc23);
        }

        // ===== tanh + store (4 consecutive hid cols -> float4) =====
        {
            float v0, v1, v2, v3;
            unpack_pair(acc01, v0, v1);
            unpack_pair(acc23, v2, v3);
            float4 o = make_float4(tanhf(v0), tanhf(v1), tanhf(v2), tanhf(v3));
            *(float4*)(out + ((size_t)(t * NL + l) * BATCH + b) * HID + row0 + rq * 4) = o;
        }

        // ===== publish =====
        __threadfence();
        __syncthreads();
        if (tid == 0) atomicAdd(&g_cnt[l * SEQ + t], 1);
    }
}

extern "C" void kernel_launch(void* const* d_in, const int* in_sizes, int n_in,
                              void* d_out, int out_size) {
    const float* x    = (const float*)d_in[0];
    const float* W_ih = (const float*)d_in[1];
    const float* W_hh = (const float*)d_in[2];
    const float* b_ih = (const float*)d_in[3];
    const float* b_hh = (const float*)d_in[4];
    float* out = (float*)d_out;

    cudaFuncSetAttribute(rnn_kernel, cudaFuncAttributeMaxDynamicSharedMemorySize, SMEM_BYTES);

    reset_kernel<<<2, 1024>>>();
    rnn_kernel<<<NL * SLICES, NTHREADS, SMEM_BYTES>>>(x, W_ih, W_hh, b_ih, b_hh, out);
}

// round 7
// speedup vs baseline: 1.8917x; 1.7562x over previous
#include <cuda_runtime.h>
#include <math.h>
#include <stdint.h>

// MultiLayerElmanRNN — persistent wavefront kernel, round 5.
// 128 CTAs (4 layers x 32 slices), 512 threads (4 warps/SMSP).
// 8-way k-split: thread (kh, rq, bq) computes 4 rows x 4 batches over a
// 64-k slice with f32x2 FFMA2; partials reduced through SMEM (aliased onto
// the act buffer). Weights live in SMEM as [rq][k][4] quads so one
// ld.shared.v2.u64 gives both row-pair operands, broadcast across the warp.

#define SEQ       512
#define BATCH     64
#define HID       512
#define NL        4
#define SLICES    32
#define ROWS      16
#define NTHREADS  512
#define AS        516                  // act row stride (floats), ≡4 mod 32
#define KH        8                    // k-split factor
#define KSLICE    64                   // k per split
#define WM_FLOATS 8192                 // per matrix: 16 rows x 512 k
#define RED_PS    18                   // reduction words per position (pad)
#define RED_KS    (64 * RED_PS)        // reduction words per kh

#define SMEM_FLOATS (2 * WM_FLOATS + BATCH * AS)
#define SMEM_BYTES  (SMEM_FLOATS * 4)  // 197632

__device__ int g_cnt[NL * SEQ];

__global__ void reset_kernel() {
    int i = blockIdx.x * blockDim.x + threadIdx.x;
    if (i < NL * SEQ) g_cnt[i] = 0;
}

__device__ __forceinline__ unsigned long long pack2(float lo, float hi) {
    unsigned long long r;
    asm("mov.b64 %0, {%1, %2};" : "=l"(r) : "f"(lo), "f"(hi));
    return r;
}
__device__ __forceinline__ void unpack2(unsigned long long p, float& lo, float& hi) {
    asm("mov.b64 {%0, %1}, %2;" : "=f"(lo), "=f"(hi) : "l"(p));
}

// One 64-k slice of one GEMM half. acc[rp*4+bj] over rows (rq*4+rp*2, +1),
// batches (bq + 16*bj).
__device__ __forceinline__ void gemm_slice(uint32_t wk, uint32_t ak,
                                           unsigned long long* acc) {
#pragma unroll 4
    for (int i = 0; i < KSLICE / 4; i++) {
        float a0x, a0y, a0z, a0w, a1x, a1y, a1z, a1w;
        float a2x, a2y, a2z, a2w, a3x, a3y, a3z, a3w;
        asm("ld.shared.v4.f32 {%0,%1,%2,%3}, [%4];"
            : "=f"(a0x), "=f"(a0y), "=f"(a0z), "=f"(a0w) : "r"(ak));
        asm("ld.shared.v4.f32 {%0,%1,%2,%3}, [%4+%5];"
            : "=f"(a1x), "=f"(a1y), "=f"(a1z), "=f"(a1w) : "r"(ak), "n"(16 * AS * 4));
        asm("ld.shared.v4.f32 {%0,%1,%2,%3}, [%4+%5];"
            : "=f"(a2x), "=f"(a2y), "=f"(a2z), "=f"(a2w) : "r"(ak), "n"(32 * AS * 4));
        asm("ld.shared.v4.f32 {%0,%1,%2,%3}, [%4+%5];"
            : "=f"(a3x), "=f"(a3y), "=f"(a3z), "=f"(a3w) : "r"(ak), "n"(48 * AS * 4));

#define KSTEP(KK, AX0, AX1, AX2, AX3)                                              \
        {                                                                          \
            unsigned long long w01, w23, d;                                        \
            asm("ld.shared.v2.u64 {%0,%1}, [%2+" #KK "];"                          \
                : "=l"(w01), "=l"(w23) : "r"(wk));                                  \
            asm("mov.b64 %0, {%1,%1};" : "=l"(d) : "f"(AX0));                      \
            asm("fma.rn.f32x2 %0, %1, %2, %3;" : "=l"(acc[0]) : "l"(w01), "l"(d), "l"(acc[0])); \
            asm("fma.rn.f32x2 %0, %1, %2, %3;" : "=l"(acc[4]) : "l"(w23), "l"(d), "l"(acc[4])); \
            asm("mov.b64 %0, {%1,%1};" : "=l"(d) : "f"(AX1));                      \
            asm("fma.rn.f32x2 %0, %1, %2, %3;" : "=l"(acc[1]) : "l"(w01), "l"(d), "l"(acc[1])); \
            asm("fma.rn.f32x2 %0, %1, %2, %3;" : "=l"(acc[5]) : "l"(w23), "l"(d), "l"(acc[5])); \
            asm("mov.b64 %0, {%1,%1};" : "=l"(d) : "f"(AX2));                      \
            asm("fma.rn.f32x2 %0, %1, %2, %3;" : "=l"(acc[2]) : "l"(w01), "l"(d), "l"(acc[2])); \
            asm("fma.rn.f32x2 %0, %1, %2, %3;" : "=l"(acc[6]) : "l"(w23), "l"(d), "l"(acc[6])); \
            asm("mov.b64 %0, {%1,%1};" : "=l"(d) : "f"(AX3));                      \
            asm("fma.rn.f32x2 %0, %1, %2, %3;" : "=l"(acc[3]) : "l"(w01), "l"(d), "l"(acc[3])); \
            asm("fma.rn.f32x2 %0, %1, %2, %3;" : "=l"(acc[7]) : "l"(w23), "l"(d), "l"(acc[7])); \
        }
        KSTEP(0,  a0x, a1x, a2x, a3x)
        KSTEP(16, a0y, a1y, a2y, a3y)
        KSTEP(32, a0z, a1z, a2z, a3z)
        KSTEP(48, a0w, a1w, a2w, a3w)
#undef KSTEP
        wk += 64;   // 4 k * 4 rows * 4B
        ak += 16;   // 4 floats
    }
}

__global__ __launch_bounds__(NTHREADS, 1)
void rnn_kernel(const float* __restrict__ x,
                const float* __restrict__ W_ih,
                const float* __restrict__ W_hh,
                const float* __restrict__ b_ih,
                const float* __restrict__ b_hh,
                float* __restrict__ out) {
    extern __shared__ float smem[];
    float* act_s = smem + 2 * WM_FLOATS;

    uint32_t sbase;
    asm("{ .reg .u64 t; cvta.to.shared.u64 t, %1; cvt.u32.u64 %0, t; }"
        : "=r"(sbase) : "l"(smem));
    const uint32_t wih_base = sbase;
    const uint32_t whh_base = sbase + WM_FLOATS * 4;
    const uint32_t act_base = sbase + 2 * WM_FLOATS * 4;
    const uint32_t red_base = act_base;                 // aliased (36KB < 129KB)

    const int l    = blockIdx.x / SLICES;
    const int s    = blockIdx.x % SLICES;
    const int tid  = threadIdx.x;
    const int row0 = s * ROWS;

    // ---- load + transpose weights into SMEM quads wq[rq][k][4] (once) ----
    for (int p = tid; p < WM_FLOATS; p += NTHREADS) {
        int k  = p & (HID - 1);
        int r  = p >> 9;                  // 0..15
        int rq = r >> 2, j = r & 3;
        int si = rq * 2048 + k * 4 + j;
        smem[si]             = W_ih[(size_t)l * HID * HID + (size_t)(row0 + r) * HID + k];
        smem[WM_FLOATS + si] = W_hh[(size_t)l * HID * HID + (size_t)(row0 + r) * HID + k];
    }

    // ---- thread coords: gemm role (kh, rq, bq) ----
    const int kh = tid >> 6;              // 0..7  (k-slice)
    const int rq = (tid >> 4) & 3;        // 0..3  (row quad)
    const int bq = tid & 15;              // 0..15 (batch lane)

    const uint32_t ak0   = act_base + ((uint32_t)bq * AS + (uint32_t)kh * KSLICE) * 4;
    const uint32_t wk_ih = wih_base + ((uint32_t)rq * 2048 + (uint32_t)kh * KSLICE * 4) * 4;
    const uint32_t wk_hh = whh_base + ((uint32_t)rq * 2048 + (uint32_t)kh * KSLICE * 4) * 4;
    const uint32_t red_st = red_base + (uint32_t)(kh * RED_KS + (rq * 16 + bq) * RED_PS) * 4;

    // ---- reduction role (pos, pair): 1 f32x2 (2 cells) per thread ----
    const int pos     = tid >> 3;         // 0..63
    const int pair    = tid & 7;          // 0..7
    const int rq_red  = pos >> 4;
    const int bq_red  = pos & 15;
    const int rp_red  = pair >> 2;
    const int bj_red  = pair & 3;
    const int row_red = row0 + rq_red * 4 + rp_red * 2;
    const int b_red   = bq_red + 16 * bj_red;
    const unsigned long long bias =
        pack2(b_ih[l * HID + row_red]     + b_hh[l * HID + row_red],
              b_ih[l * HID + row_red + 1] + b_hh[l * HID + row_red + 1]);
    const uint32_t red_ld = red_base + (uint32_t)(pos * RED_PS + pair * 2) * 4;

    __syncthreads();

    volatile int* cnt = g_cnt;

    for (int t = 0; t < SEQ; t++) {
        unsigned long long acc[8];
#pragma unroll
        for (int j = 0; j < 8; j++) acc[j] = 0ULL;

        // ===== recurrent half first (dep: (t-1, l) only) =====
        if (t > 0) {
            if (tid == 0) {
                while (cnt[l * SEQ + (t - 1)] < SLICES) __nanosleep(20);
            }
            __syncthreads();
            __threadfence();
            const float* src = out + ((size_t)(t - 1) * NL + l) * (BATCH * HID);
#pragma unroll
            for (int i = 0; i < 16; i++) {
                int p  = tid + i * NTHREADS;      // 0..8191 float4 units
                int bb = p >> 7;
                int kq = p & 127;
                float4 v = *(const float4*)(src + (size_t)bb * HID + kq * 4);
                *(float4*)&act_s[bb * AS + kq * 4] = v;
            }
            __syncthreads();
            gemm_slice(wk_hh, ak0, acc);
        }

        // ===== input half (dep: (t, l-1)) =====
        if (l > 0) {
            if (tid == 0) {
                while (cnt[(l - 1) * SEQ + t] < SLICES) __nanosleep(20);
            }
        }
        __syncthreads();      // act_s free after hh gemm + wait published
        __threadfence();
        {
            const float* src = (l == 0)
                ? (x + (size_t)t * BATCH * HID)
                : (out + ((size_t)t * NL + (l - 1)) * (BATCH * HID));
#pragma unroll
            for (int i = 0; i < 16; i++) {
                int p  = tid + i * NTHREADS;
                int bb = p >> 7;
                int kq = p & 127;
                float4 v = *(const float4*)(src + (size_t)bb * HID + kq * 4);
                *(float4*)&act_s[bb * AS + kq * 4] = v;
            }
            __syncthreads();
            gemm_slice(wk_ih, ak0, acc);
        }

        // ===== cross-kh reduction through SMEM (aliases act_s) =====
        __syncthreads();                   // all act reads done before alias
#pragma unroll
        for (int j = 0; j < 8; j++) {
            asm volatile("st.shared.b64 [%0], %1;"
                         :: "r"(red_st + (uint32_t)j * 8), "l"(acc[j]));
        }
        __syncthreads();

        {
            unsigned long long sum = bias;
#pragma unroll
            for (int k2 = 0; k2 < KH; k2++) {
                unsigned long long v;
                asm("ld.shared.b64 %0, [%1];"
                    : "=l"(v) : "r"(red_ld + (uint32_t)(k2 * RED_KS) * 4));
                asm("add.rn.f32x2 %0, %1, %2;" : "=l"(sum) : "l"(sum), "l"(v));
            }
            float lo, hi;
            unpack2(sum, lo, hi);
            float2 o = make_float2(tanhf(lo), tanhf(hi));
            *(float2*)(out + ((size_t)(t * NL + l) * BATCH + b_red) * HID + row_red) = o;
        }

        // ===== publish =====
        __threadfence();
        __syncthreads();
        if (tid == 0) atomicAdd(&g_cnt[l * SEQ + t], 1);
    }
}

extern "C" void kernel_launch(void* const* d_in, const int* in_sizes, int n_in,
                              void* d_out, int out_size) {
    const float* x    = (const float*)d_in[0];
    const float* W_ih = (const float*)d_in[1];
    const float* W_hh = (const float*)d_in[2];
    const float* b_ih = (const float*)d_in[3];
    const float* b_hh = (const float*)d_in[4];
    float* out = (float*)d_out;

    cudaFuncSetAttribute(rnn_kernel, cudaFuncAttributeMaxDynamicSharedMemorySize, SMEM_BYTES);

    reset_kernel<<<2, 1024>>>();
    rnn_kernel<<<NL * SLICES, NTHREADS, SMEM_BYTES>>>(x, W_ih, W_hh, b_ih, b_hh, out);
}

// round 11
// speedup vs baseline: 2.3680x; 1.2518x over previous
#include <cuda_runtime.h>
#include <math.h>
#include <stdint.h>

// MultiLayerElmanRNN — round 10: mma.sync (HMMA) split-bf16 engine on the
// proven wavefront skeleton. tcgen05 unavailable (toolchain targets sm_103,
// not sm_103a), so tensor cores are reached via standard mma.sync.m16n8k16.
//
// Per cell (l, t), per CTA (16 hidden rows):
//   A  = [act_hi(64 batches); act_lo(64)]  (128 x 512 bf16, padded rows)
//   B  = W_hi / W_lo (16 x 512 bf16 each), ih and hh variants
//   D1 = A @ W_hi^T, D2 = A @ W_lo^T accumulated in registers across both
//   halves; epilogue sums D1[b]+D1[b+64]+D2[b]+D2[b+64] (all split terms),
//   adds bias, tanh, stores fp32 to d_out.
// 16 warps = (mt 0..7, kh 0..1); warp tile M=16, N=16, K=256 per half.

#define SEQ    512
#define BATCH  64
#define HID    512
#define NL     4
#define SLICES 32
#define ROWS   16
#define NT     512

#define AST 1040                 // bf16 row stride bytes (1024 + 16 pad): conflict-free ldmatrix
#define A_O        0             // A: 128 rows x AST = 133120 B (aliased by epilogue exchange)
#define BIH_HI_O   133120        // each W matrix: 16 rows x AST = 16640 B
#define BIH_LO_O   149760
#define BHH_HI_O   166400
#define BHH_LO_O   183040
#define BIAS_O     199680        // 16 floats
#define SMEM_BYTES 199744

__device__ int g_cnt[NL * SEQ];

__global__ void reset_kernel() {
    int i = blockIdx.x * blockDim.x + threadIdx.x;
    if (i < NL * SEQ) g_cnt[i] = 0;
}

// fp32 pair -> bf16x2 hi / lo (lo = residual), lo-half = first element.
__device__ __forceinline__ void split2(float a, float b, uint32_t& hi, uint32_t& lo) {
    asm("cvt.rn.bf16x2.f32 %0, %1, %2;" : "=r"(hi) : "f"(b), "f"(a));
    float ha = __uint_as_float(hi << 16);
    float hb = __uint_as_float(hi & 0xFFFF0000u);
    asm("cvt.rn.bf16x2.f32 %0, %1, %2;" : "=r"(lo) : "f"(b - hb), "f"(a - ha));
}

__device__ __forceinline__ void split8_store(float4 v0, float4 v1, char* hi_p, char* lo_p) {
    uint4 H, L;
    split2(v0.x, v0.y, H.x, L.x);
    split2(v0.z, v0.w, H.y, L.y);
    split2(v1.x, v1.y, H.z, L.z);
    split2(v1.z, v1.w, H.w, L.w);
    *(uint4*)hi_p = H;
    *(uint4*)lo_p = L;
}

#define LDSM4(r0, r1, r2, r3, addr)                                         \
    asm volatile("ldmatrix.sync.aligned.m8n8.x4.shared.b16 {%0,%1,%2,%3}, [%4];" \
        : "=r"(r0), "=r"(r1), "=r"(r2), "=r"(r3) : "r"(addr))

#define MMA16816(c, a0, a1, a2, a3, b0, b1)                                 \
    asm volatile("mma.sync.aligned.m16n8k16.row.col.f32.bf16.bf16.f32 "      \
        "{%0,%1,%2,%3}, {%4,%5,%6,%7}, {%8,%9}, {%0,%1,%2,%3};"              \
        : "+f"((c)[0]), "+f"((c)[1]), "+f"((c)[2]), "+f"((c)[3])             \
        : "r"(a0), "r"(a1), "r"(a2), "r"(a3), "r"(b0), "r"(b1))

// One half (K=256 slice for this warp): 16 k-steps.
// acc[0..3]=hi nf0, [4..7]=hi nf1, [8..11]=lo nf0, [12..15]=lo nf1.
__device__ __forceinline__ void mma_pass(uint32_t aa, uint32_t bh, uint32_t bl,
                                         float* acc) {
#pragma unroll
    for (int kk = 0; kk < 16; kk++) {
        uint32_t a0, a1, a2, a3, h0, h1, h2, h3, l0, l1, l2, l3;
        LDSM4(a0, a1, a2, a3, aa);
        LDSM4(h0, h1, h2, h3, bh);
        LDSM4(l0, l1, l2, l3, bl);
        MMA16816(acc + 0,  a0, a1, a2, a3, h0, h1);
        MMA16816(acc + 4,  a0, a1, a2, a3, h2, h3);
        MMA16816(acc + 8,  a0, a1, a2, a3, l0, l1);
        MMA16816(acc + 12, a0, a1, a2, a3, l2, l3);
        aa += 32;
        bh += 32;
        bl += 32;
    }
}

// Stage one half's fp32 activations [64][512] as split bf16 into A
// (rows b = hi, b+64 = lo), padded row-major (no swizzle: ldmatrix shuffles).
__device__ __forceinline__ void stage_A(const float* __restrict__ src, char* sm, int tid) {
    int b  = tid >> 3;
    int kb = tid & 7;
    const float* row = src + (size_t)b * HID;
    char* hi_row = sm + A_O + (size_t)b * AST;
    char* lo_row = sm + A_O + (size_t)(b + 64) * AST;
#pragma unroll
    for (int i = 0; i < 8; i++) {
        int k0 = (kb + (i << 3)) << 3;
        float4 v0 = *(const float4*)(row + k0);
        float4 v1 = *(const float4*)(row + k0 + 4);
        split8_store(v0, v1, hi_row + k0 * 2, lo_row + k0 * 2);
    }
}

__global__ __launch_bounds__(NT, 1)
void rnn_kernel(const float* __restrict__ x,
                const float* __restrict__ W_ih,
                const float* __restrict__ W_hh,
                const float* __restrict__ b_ih,
                const float* __restrict__ b_hh,
                float* __restrict__ out) {
    extern __shared__ char sm[];
    uint32_t sbase;
    asm("{ .reg .u64 t; cvta.to.shared.u64 t, %1; cvt.u32.u64 %0, t; }"
        : "=r"(sbase) : "l"(sm));

    const int l    = blockIdx.x / SLICES;
    const int s    = blockIdx.x % SLICES;
    const int tid  = threadIdx.x;
    const int wid  = tid >> 5;
    const int lane = tid & 31;
    const int row0 = s * ROWS;

    // ---- weights: split bf16 hi/lo, padded row-major (once) ----
    for (int idx = tid; idx < ROWS * 64; idx += NT) {
        int row = idx >> 6;
        int k0  = (idx & 63) << 3;
        const float* wih = W_ih + ((size_t)l * HID + row0 + row) * HID + k0;
        const float* whh = W_hh + ((size_t)l * HID + row0 + row) * HID + k0;
        float4 a0 = *(const float4*)wih;
        float4 a1 = *(const float4*)(wih + 4);
        split8_store(a0, a1, sm + BIH_HI_O + (size_t)row * AST + k0 * 2,
                             sm + BIH_LO_O + (size_t)row * AST + k0 * 2);
        float4 c0 = *(const float4*)whh;
        float4 c1 = *(const float4*)(whh + 4);
        split8_store(c0, c1, sm + BHH_HI_O + (size_t)row * AST + k0 * 2,
                             sm + BHH_LO_O + (size_t)row * AST + k0 * 2);
    }
    if (tid < ROWS) {
        ((float*)(sm + BIAS_O))[tid] = b_ih[l * HID + row0 + tid] + b_hh[l * HID + row0 + tid];
    }

    // ---- per-warp / per-lane fragment addresses ----
    const int mt = wid & 7;          // m-tile (16 stacked rows)
    const int kh = wid >> 3;         // k-half (256 k)
    const int tile = lane >> 3;
    const int tr   = lane & 7;
    // A tiles: [m0k0][m8k0][m0k8][m8k8]
    const uint32_t a_lane = sbase + A_O
        + (uint32_t)(mt * 16 + ((tile & 1) << 3) + tr) * AST
        + (uint32_t)(kh * 512 + ((tile >> 1) << 4));
    // B tiles: [n0k0][n0k8][n8k0][n8k8]
    const uint32_t b_off = (uint32_t)(((tile >> 1) << 3) + tr) * AST
        + (uint32_t)(kh * 512 + ((tile & 1) << 4));

    __syncthreads();

    volatile int* cnt = g_cnt;
    float* exf = (float*)(sm + A_O);          // epilogue exchange aliases A
    const float* bs = (const float*)(sm + BIAS_O);

    for (int t = 0; t < SEQ; t++) {
        float acc[16];
#pragma unroll
        for (int j = 0; j < 16; j++) acc[j] = 0.0f;

        // ===== recurrent half first (dep: (t-1, l)) =====
        if (t > 0) {
            if (tid == 0) {
                while (cnt[l * SEQ + (t - 1)] < SLICES) __nanosleep(20);
            }
            __syncthreads();
            __threadfence();
            stage_A(out + ((size_t)(t - 1) * NL + l) * (BATCH * HID), sm, tid);
            __syncthreads();
            mma_pass(a_lane, sbase + BHH_HI_O + b_off, sbase + BHH_LO_O + b_off, acc);
        }

        // ===== input half (dep: (t, l-1)) =====
        if (l > 0) {
            if (tid == 0) {
                while (cnt[(l - 1) * SEQ + t] < SLICES) __nanosleep(20);
            }
        }
        __syncthreads();                    // A free after hh pass + wait published
        __threadfence();
        {
            const float* src = (l == 0)
                ? (x + (size_t)t * BATCH * HID)
                : (out + ((size_t)t * NL + (l - 1)) * (BATCH * HID));
            stage_A(src, sm, tid);
        }
        __syncthreads();
        mma_pass(a_lane, sbase + BIH_HI_O + b_off, sbase + BIH_LO_O + b_off, acc);

        // ===== epilogue: exchange (aliases A), fold, bias, tanh, store =====
        __syncthreads();                    // all ldmatrix reads of A done
        {
            // in-register mat fold: S = D1 + D2 for this warp's 16x16 tile
            float s0[4], s1[4];
#pragma unroll
            for (int j = 0; j < 4; j++) {
                s0[j] = acc[j]     + acc[8 + j];    // nf0
                s1[j] = acc[4 + j] + acc[12 + j];   // nf1
            }
            float* base = exf + (size_t)(kh * 8 + mt) * 256;   // tile = 256 floats
            int g  = lane >> 2;
            int tq = lane & 3;
            *(float2*)(base + g * 16       + tq * 2)     = make_float2(s0[0], s0[1]);
            *(float2*)(base + (g + 8) * 16 + tq * 2)     = make_float2(s0[2], s0[3]);
            *(float2*)(base + g * 16       + 8 + tq * 2) = make_float2(s1[0], s1[1]);
            *(float2*)(base + (g + 8) * 16 + 8 + tq * 2) = make_float2(s1[2], s1[3]);
        }
        __syncthreads();
        {
            int b  = tid >> 3;
            int r  = (tid & 7) * 2;
            int t1 = b >> 4;                 // kh0, hi-part tile
            int rw = (b & 15) * 16 + r;
            float2 vA = *(float2*)(exf + (size_t)t1 * 256 + rw);         // kh0 hi
            float2 vB = *(float2*)(exf + (size_t)(t1 + 4) * 256 + rw);   // kh0 lo-rows
            float2 vC = *(float2*)(exf + (size_t)(t1 + 8) * 256 + rw);   // kh1 hi
            float2 vD = *(float2*)(exf + (size_t)(t1 + 12) * 256 + rw);  // kh1 lo-rows
            float o0 = tanhf(vA.x + vB.x + vC.x + vD.x + bs[r]);
            float o1 = tanhf(vA.y + vB.y + vC.y + vD.y + bs[r + 1]);
            *(float2*)(out + ((size_t)(t * NL + l) * BATCH + b) * HID + row0 + r)
                = make_float2(o0, o1);
        }

        // ===== publish =====
        __threadfence();
        __syncthreads();
        if (tid == 0) atomicAdd(&g_cnt[l * SEQ + t], 1);
    }
}

extern "C" void kernel_launch(void* const* d_in, const int* in_sizes, int n_in,
                              void* d_out, int out_size) {
    const float* x    = (const float*)d_in[0];
    const float* W_ih = (const float*)d_in[1];
    const float* W_hh = (const float*)d_in[2];
    const float* b_ih = (const float*)d_in[3];
    const float* b_hh = (const float*)d_in[4];
    float* out = (float*)d_out;

    cudaFuncSetAttribute(rnn_kernel, cudaFuncAttributeMaxDynamicSharedMemorySize, SMEM_BYTES);

    reset_kernel<<<2, 1024>>>();
    rnn_kernel<<<NL * SLICES, NT, SMEM_BYTES>>>(x, W_ih, W_hh, b_ih, b_hh, out);
}